// round 4
// baseline (speedup 1.0000x reference)
#include <cuda_runtime.h>
#include <cstdint>
#include <cstddef>

#define NB 64
#define NC 256
#define NL 4096
#define LT 4

// ---------------- scratch (device globals; no allocation allowed) ----------
__device__ float d_M [NC * NC];                 // Wq^T Wk / sqrt(C)
__device__ float d_W2[NC * NC];                 // Wout @ Wc
__device__ float d_g   [(size_t)NB * NC * NL];  // M @ x
__device__ float d_v   [(size_t)NB * NC * NL];  // Wv @ x
__device__ float d_virt[(size_t)NB * NC * NL];  // attention output
__device__ float d_mean[NB];
__device__ float d_rstd[NB];

// ---------------- K0: M = Wq^T Wk / 16 -------------------------------------
__global__ void k0_M(const float* __restrict__ Wq, const float* __restrict__ Wk) {
    __shared__ float sA[16][17], sB[16][17];
    int tx = threadIdx.x, ty = threadIdx.y;
    int c1 = blockIdx.y * 16 + ty;
    int c2 = blockIdx.x * 16 + tx;
    float acc = 0.f;
    for (int o0 = 0; o0 < NC; o0 += 16) {
        sA[ty][tx] = Wq[(o0 + ty) * NC + blockIdx.y * 16 + tx];
        sB[ty][tx] = Wk[(o0 + ty) * NC + blockIdx.x * 16 + tx];
        __syncthreads();
#pragma unroll
        for (int i = 0; i < 16; i++) acc += sA[i][ty] * sB[i][tx];
        __syncthreads();
    }
    d_M[c1 * NC + c2] = acc * 0.0625f;  // 1/sqrt(256)
}

// ---------------- K0b: W2 = Wout @ Wc --------------------------------------
__global__ void k0_W2(const float* __restrict__ Wout, const float* __restrict__ Wc) {
    __shared__ float sA[16][17], sB[16][17];
    int tx = threadIdx.x, ty = threadIdx.y;
    int o = blockIdx.y * 16 + ty;
    int c = blockIdx.x * 16 + tx;
    float acc = 0.f;
    for (int m0 = 0; m0 < NC; m0 += 16) {
        sA[ty][tx] = Wout[o * NC + m0 + tx];
        sB[ty][tx] = Wc[(m0 + ty) * NC + blockIdx.x * 16 + tx];
        __syncthreads();
#pragma unroll
        for (int i = 0; i < 16; i++) acc += sA[ty][i] * sB[i][tx];
        __syncthreads();
    }
    d_W2[o * NC + c] = acc;
}

// ---------------- K1: [M ; Wv] @ x[b]  ->  g, v ----------------------------
// grid (L/64, 512/128, B), 256 threads, tile 128(m) x 64(n), K=256
__global__ __launch_bounds__(256) void k_proj(const float* __restrict__ x,
                                              const float* __restrict__ Wv) {
    __shared__ float As[16][128];
    __shared__ float Bs[16][64];
    int tid = threadIdx.x;
    int b   = blockIdx.z;
    int m0  = blockIdx.y * 128;           // 0,128 -> M/g ; 256,384 -> Wv/v
    int l0  = blockIdx.x * 64;
    const float* A = (m0 < 256) ? d_M : Wv;
    float*       Y = (m0 < 256) ? d_g : d_v;
    int mb = m0 & 255;
    const float* B = x + (size_t)b * NC * NL;

    int tn = tid & 15, tm = tid >> 4;
    float acc[8][4];
#pragma unroll
    for (int i = 0; i < 8; i++)
#pragma unroll
        for (int j = 0; j < 4; j++) acc[i][j] = 0.f;

    int arow = tid >> 1;
    int kseg = (tid & 1) * 8;
    int brr  = tid >> 4;
    int bcc  = (tid & 15) * 4;

    for (int k0 = 0; k0 < NC; k0 += 16) {
        const float* ap = A + (size_t)(mb + arow) * NC + k0 + kseg;
        float4 a0 = *(const float4*)ap;
        float4 a1 = *(const float4*)(ap + 4);
        As[kseg + 0][arow] = a0.x; As[kseg + 1][arow] = a0.y;
        As[kseg + 2][arow] = a0.z; As[kseg + 3][arow] = a0.w;
        As[kseg + 4][arow] = a1.x; As[kseg + 5][arow] = a1.y;
        As[kseg + 6][arow] = a1.z; As[kseg + 7][arow] = a1.w;
        *(float4*)&Bs[brr][bcc] =
            *(const float4*)(B + (size_t)(k0 + brr) * NL + l0 + bcc);
        __syncthreads();
#pragma unroll
        for (int kk = 0; kk < 16; kk++) {
            float4 r0 = *(float4*)&As[kk][tm * 8];
            float4 r1 = *(float4*)&As[kk][tm * 8 + 4];
            float4 bv = *(float4*)&Bs[kk][tn * 4];
            float am[8] = {r0.x, r0.y, r0.z, r0.w, r1.x, r1.y, r1.z, r1.w};
            float bn[4] = {bv.x, bv.y, bv.z, bv.w};
#pragma unroll
            for (int i = 0; i < 8; i++)
#pragma unroll
                for (int j = 0; j < 4; j++) acc[i][j] += am[i] * bn[j];
        }
        __syncthreads();
    }
#pragma unroll
    for (int i = 0; i < 8; i++) {
        float4 o4 = make_float4(acc[i][0], acc[i][1], acc[i][2], acc[i][3]);
        *(float4*)(Y + ((size_t)b * NC + mb + tm * 8 + i) * NL + l0 + tn * 4) = o4;
    }
}

// ---------------- K2: attention per l-tile (LT=4) --------------------------
// smem: sP [64][260] (att, padded) + union{ sX[64][36], sG[64][36] | sV[64][132] }
#define SP_STR 260
#define SX_STR 36
#define SV_STR 132
#define K2_SMEM ((64 * SP_STR + 64 * SV_STR) * 4)

__global__ __launch_bounds__(256, 2) void k2_attn(const float* __restrict__ x) {
    extern __shared__ float smem[];
    float* sP = smem;
    float* sX = smem + 64 * SP_STR;
    float* sG = sX + 64 * SX_STR;
    float* sV = smem + 64 * SP_STR;   // reuses phase-1 region

    int tid = threadIdx.x;
    int lt  = blockIdx.x * LT;
    int tb  = tid & 15;
    int td  = tid >> 4;

    // ---- phase 1: att[b,d,l] = sum_c x[b,c,l] * g[d,c,l] ----
    float acc[4][4][4];
#pragma unroll
    for (int i = 0; i < 4; i++)
#pragma unroll
        for (int j = 0; j < 4; j++)
#pragma unroll
            for (int l = 0; l < 4; l++) acc[i][j][l] = 0.f;

    for (int c0 = 0; c0 < NC; c0 += 8) {
#pragma unroll
        for (int j = 0; j < 2; j++) {
            int t  = tid + j * 256;
            int bb = t >> 3, cc = t & 7;
            *(float4*)&sX[bb * SX_STR + cc * 4] =
                *(const float4*)(x   + ((size_t)bb * NC + c0 + cc) * NL + lt);
            *(float4*)&sG[bb * SX_STR + cc * 4] =
                *(const float4*)(d_g + ((size_t)bb * NC + c0 + cc) * NL + lt);
        }
        __syncthreads();
#pragma unroll
        for (int cc = 0; cc < 8; cc++) {
            float4 xv[4], gv[4];
#pragma unroll
            for (int i = 0; i < 4; i++)
                xv[i] = *(float4*)&sX[(tb + 16 * i) * SX_STR + cc * 4];
#pragma unroll
            for (int i = 0; i < 4; i++)
                gv[i] = *(float4*)&sG[(td + 16 * i) * SX_STR + cc * 4];
#pragma unroll
            for (int bi = 0; bi < 4; bi++)
#pragma unroll
                for (int di = 0; di < 4; di++) {
                    acc[bi][di][0] += xv[bi].x * gv[di].x;
                    acc[bi][di][1] += xv[bi].y * gv[di].y;
                    acc[bi][di][2] += xv[bi].z * gv[di].z;
                    acc[bi][di][3] += xv[bi].w * gv[di].w;
                }
        }
        __syncthreads();
    }
#pragma unroll
    for (int bi = 0; bi < 4; bi++)
#pragma unroll
        for (int di = 0; di < 4; di++)
#pragma unroll
            for (int l = 0; l < 4; l++)
                sP[(tb + 16 * bi) * SP_STR + (td + 16 * di) * 4 + l] = acc[bi][di][l];
    __syncthreads();

    // ---- phase 2: softmax over d for each (b,l) ----
    {
        int b = tid >> 2, l = tid & 3;
        float* row = sP + b * SP_STR + l;
        float mx = -1e30f;
#pragma unroll 8
        for (int d = 0; d < 64; d++) mx = fmaxf(mx, row[d * 4]);
        float s = 0.f;
#pragma unroll 8
        for (int d = 0; d < 64; d++) {
            float e = __expf(row[d * 4] - mx);
            row[d * 4] = e;
            s += e;
        }
        float inv = 1.f / s;
#pragma unroll 8
        for (int d = 0; d < 64; d++) row[d * 4] *= inv;
    }
    __syncthreads();

    // ---- phase 3: virt[b,c,l] = sum_d P[b,d,l] * v[d,c,l] ----
    int tc = tid >> 4;
    for (int c0 = 0; c0 < NC; c0 += 32) {
#pragma unroll
        for (int j = 0; j < 8; j++) {
            int t  = tid + j * 256;
            int dd = t >> 5, ci = t & 31;
            *(float4*)&sV[dd * SV_STR + ci * 4] =
                *(const float4*)(d_v + ((size_t)dd * NC + c0 + ci) * NL + lt);
        }
        __syncthreads();
        float a3[4][2][4];
#pragma unroll
        for (int i = 0; i < 4; i++)
#pragma unroll
            for (int j = 0; j < 2; j++)
#pragma unroll
                for (int l = 0; l < 4; l++) a3[i][j][l] = 0.f;
#pragma unroll 4
        for (int d = 0; d < 64; d++) {
            float4 p[4];
#pragma unroll
            for (int i = 0; i < 4; i++)
                p[i] = *(float4*)&sP[(tb + 16 * i) * SP_STR + d * 4];
            float4 vv[2];
#pragma unroll
            for (int i = 0; i < 2; i++)
                vv[i] = *(float4*)&sV[d * SV_STR + (tc + 16 * i) * 4];
#pragma unroll
            for (int bi = 0; bi < 4; bi++)
#pragma unroll
                for (int ci = 0; ci < 2; ci++) {
                    a3[bi][ci][0] += p[bi].x * vv[ci].x;
                    a3[bi][ci][1] += p[bi].y * vv[ci].y;
                    a3[bi][ci][2] += p[bi].z * vv[ci].z;
                    a3[bi][ci][3] += p[bi].w * vv[ci].w;
                }
        }
#pragma unroll
        for (int bi = 0; bi < 4; bi++)
#pragma unroll
            for (int ci = 0; ci < 2; ci++) {
                float4 o4 = make_float4(a3[bi][ci][0], a3[bi][ci][1],
                                        a3[bi][ci][2], a3[bi][ci][3]);
                *(float4*)(d_virt + ((size_t)(tb + 16 * bi) * NC + c0 + tc + 16 * ci) * NL + lt) = o4;
            }
        __syncthreads();
    }
}

// ---------------- K3: per-batch GroupNorm stats (deterministic) ------------
__global__ void k3_stats() {
    int b   = blockIdx.x;
    int tid = threadIdx.x;
    const float4* p = (const float4*)(d_virt + (size_t)b * NC * NL);
    float s = 0.f, q = 0.f;
    for (int j = 0; j < 1024; j++) {
        float4 v = p[tid + j * 256];
        s += v.x + v.y + v.z + v.w;
        q += v.x * v.x + v.y * v.y + v.z * v.z + v.w * v.w;
    }
    __shared__ float ss[256], sq[256];
    ss[tid] = s; sq[tid] = q;
    __syncthreads();
    for (int st = 128; st > 0; st >>= 1) {
        if (tid < st) { ss[tid] += ss[tid + st]; sq[tid] += sq[tid + st]; }
        __syncthreads();
    }
    if (tid == 0) {
        float N    = (float)(NC * NL);
        float mean = ss[0] / N;
        float var  = sq[0] / N - mean * mean;
        d_mean[b] = mean;
        d_rstd[b] = rsqrtf(var + 1e-5f);
    }
}

// ---------------- K4: out = [Wout | W2] @ [x ; relu(gn(virt))] -------------
// grid (L/64, 256/128, B), K=512
__global__ __launch_bounds__(256) void k4_out(const float* __restrict__ x,
                                              const float* __restrict__ Wout,
                                              const float* __restrict__ gamma,
                                              const float* __restrict__ beta,
                                              float* __restrict__ out) {
    __shared__ float As[16][128];
    __shared__ float Bs[16][64];
    int tid = threadIdx.x;
    int b   = blockIdx.z;
    int m0  = blockIdx.y * 128;
    int l0  = blockIdx.x * 64;
    float mn = d_mean[b];
    float rs = d_rstd[b];

    int tn = tid & 15, tm = tid >> 4;
    float acc[8][4];
#pragma unroll
    for (int i = 0; i < 8; i++)
#pragma unroll
        for (int j = 0; j < 4; j++) acc[i][j] = 0.f;

    int arow = tid >> 1;
    int kseg = (tid & 1) * 8;
    int brr  = tid >> 4;
    int bcc  = (tid & 15) * 4;

    for (int k0 = 0; k0 < 2 * NC; k0 += 16) {
        const float* A = (k0 < 256) ? Wout : d_W2;
        const float* ap = A + (size_t)(m0 + arow) * NC + (k0 & 255) + kseg;
        float4 a0 = *(const float4*)ap;
        float4 a1 = *(const float4*)(ap + 4);
        As[kseg + 0][arow] = a0.x; As[kseg + 1][arow] = a0.y;
        As[kseg + 2][arow] = a0.z; As[kseg + 3][arow] = a0.w;
        As[kseg + 4][arow] = a1.x; As[kseg + 5][arow] = a1.y;
        As[kseg + 6][arow] = a1.z; As[kseg + 7][arow] = a1.w;

        int kr = k0 + brr;
        float4 bv;
        if (kr < 256) {
            bv = *(const float4*)(x + ((size_t)b * NC + kr) * NL + l0 + bcc);
        } else {
            int c = kr - 256;
            float4 v4 = *(const float4*)(d_virt + ((size_t)b * NC + c) * NL + l0 + bcc);
            float gsc = gamma[c] * rs;
            float bt  = beta[c] - mn * gsc;
            bv.x = fmaxf(fmaf(v4.x, gsc, bt), 0.f);
            bv.y = fmaxf(fmaf(v4.y, gsc, bt), 0.f);
            bv.z = fmaxf(fmaf(v4.z, gsc, bt), 0.f);
            bv.w = fmaxf(fmaf(v4.w, gsc, bt), 0.f);
        }
        *(float4*)&Bs[brr][bcc] = bv;
        __syncthreads();
#pragma unroll
        for (int kk = 0; kk < 16; kk++) {
            float4 r0 = *(float4*)&As[kk][tm * 8];
            float4 r1 = *(float4*)&As[kk][tm * 8 + 4];
            float4 b4 = *(float4*)&Bs[kk][tn * 4];
            float am[8] = {r0.x, r0.y, r0.z, r0.w, r1.x, r1.y, r1.z, r1.w};
            float bn[4] = {b4.x, b4.y, b4.z, b4.w};
#pragma unroll
            for (int i = 0; i < 8; i++)
#pragma unroll
                for (int j = 0; j < 4; j++) acc[i][j] += am[i] * bn[j];
        }
        __syncthreads();
    }
#pragma unroll
    for (int i = 0; i < 8; i++) {
        float4 o4 = make_float4(acc[i][0], acc[i][1], acc[i][2], acc[i][3]);
        *(float4*)(out + ((size_t)b * NC + m0 + tm * 8 + i) * NL + l0 + tn * 4) = o4;
    }
}

// ---------------- launch ----------------------------------------------------
extern "C" void kernel_launch(void* const* d_in, const int* in_sizes, int n_in,
                              void* d_out, int out_size) {
    const float* x     = (const float*)d_in[0];
    const float* Wq    = (const float*)d_in[1];
    const float* Wk    = (const float*)d_in[2];
    const float* Wv    = (const float*)d_in[3];
    const float* Wc    = (const float*)d_in[4];
    const float* Wout  = (const float*)d_in[5];
    const float* gamma = (const float*)d_in[6];
    const float* beta  = (const float*)d_in[7];
    float* out = (float*)d_out;

    cudaFuncSetAttribute(k2_attn, cudaFuncAttributeMaxDynamicSharedMemorySize, K2_SMEM);

    dim3 b16(16, 16);
    k0_M <<<dim3(16, 16), b16>>>(Wq, Wk);
    k0_W2<<<dim3(16, 16), b16>>>(Wout, Wc);
    k_proj<<<dim3(NL / 64, 4, NB), 256>>>(x, Wv);
    k2_attn<<<NL / LT, 256, K2_SMEM>>>(x);
    k3_stats<<<NB, 256>>>();
    k4_out<<<dim3(NL / 64, 2, NB), 256>>>(x, Wout, gamma, beta, out);
}

// round 9
// speedup vs baseline: 1.5217x; 1.5217x over previous
#include <cuda_runtime.h>
#include <cstdint>
#include <cstddef>

#define NB 64
#define NC 256
#define NL 4096
#define LT 4

// ---------------- scratch (device globals; no allocation allowed) ----------
__device__ float d_M [NC * NC];                 // Wq^T Wk / sqrt(C)
__device__ float d_W2[NC * NC];                 // Wout @ Wc
__device__ float d_g   [(size_t)NB * NC * NL];  // M @ x
__device__ float d_v   [(size_t)NB * NC * NL];  // Wv @ x
__device__ float d_virt[(size_t)NB * NC * NL];  // attention output
__device__ float d_mean[NB];
__device__ float d_rstd[NB];

// ---------------- helpers ---------------------------------------------------
__device__ __forceinline__ uint32_t f2tf(float v) {
    uint32_t u;
    asm("cvt.rna.tf32.f32 %0, %1;" : "=r"(u) : "f"(v));
    return u;
}
__device__ __forceinline__ void mma_tf32(float* c, const uint32_t* a,
                                         const uint32_t* b) {
    asm volatile(
        "mma.sync.aligned.m16n8k8.row.col.f32.tf32.tf32.f32 "
        "{%0,%1,%2,%3}, {%4,%5,%6,%7}, {%8,%9}, {%0,%1,%2,%3};"
        : "+f"(c[0]), "+f"(c[1]), "+f"(c[2]), "+f"(c[3])
        : "r"(a[0]), "r"(a[1]), "r"(a[2]), "r"(a[3]), "r"(b[0]), "r"(b[1]));
}

// ---------------- K0: M = Wq^T Wk / 16 -------------------------------------
__global__ void k0_M(const float* __restrict__ Wq, const float* __restrict__ Wk) {
    __shared__ float sA[16][17], sB[16][17];
    int tx = threadIdx.x, ty = threadIdx.y;
    int c1 = blockIdx.y * 16 + ty;
    int c2 = blockIdx.x * 16 + tx;
    float acc = 0.f;
    for (int o0 = 0; o0 < NC; o0 += 16) {
        sA[ty][tx] = Wq[(o0 + ty) * NC + blockIdx.y * 16 + tx];
        sB[ty][tx] = Wk[(o0 + ty) * NC + blockIdx.x * 16 + tx];
        __syncthreads();
#pragma unroll
        for (int i = 0; i < 16; i++) acc += sA[i][ty] * sB[i][tx];
        __syncthreads();
    }
    d_M[c1 * NC + c2] = acc * 0.0625f;
}

// ---------------- K0b: W2 = Wout @ Wc --------------------------------------
__global__ void k0_W2(const float* __restrict__ Wout, const float* __restrict__ Wc) {
    __shared__ float sA[16][17], sB[16][17];
    int tx = threadIdx.x, ty = threadIdx.y;
    int o = blockIdx.y * 16 + ty;
    int c = blockIdx.x * 16 + tx;
    float acc = 0.f;
    for (int m0 = 0; m0 < NC; m0 += 16) {
        sA[ty][tx] = Wout[o * NC + m0 + tx];
        sB[ty][tx] = Wc[(m0 + ty) * NC + blockIdx.x * 16 + tx];
        __syncthreads();
#pragma unroll
        for (int i = 0; i < 16; i++) acc += sA[ty][i] * sB[i][tx];
        __syncthreads();
    }
    d_W2[o * NC + c] = acc;
}

// ---------------- TF32 tensor-core GEMM ------------------------------------
// mode 0: Y[512,L] = [M ; Wv] @ x[b]          -> d_g / d_v   (K = 256)
// mode 1: out[256,L] = [Wout|W2] @ [x ; relu(gn(virt))]      (K = 512)
// CTA tile 128(m) x 128(l), k-chunk 32, 8 warps (2m x 4n), warp tile 64x32.
__global__ __launch_bounds__(256, 2) void k_gemm(int mode, float* __restrict__ out,
                                                 const float* __restrict__ Wv,
                                                 const float* __restrict__ x,
                                                 const float* __restrict__ Wout,
                                                 const float* __restrict__ gamma,
                                                 const float* __restrict__ beta) {
    __shared__ float As[128][36];   // [m][k]   (4g+tg)&31 bijective -> no conflicts
    __shared__ float Bs[32][136];   // [k][l]   (8tg+g)&31 bijective -> no conflicts

    int tid = threadIdx.x;
    int b   = blockIdx.z;
    int l0  = blockIdx.y * 128;
    int m0  = blockIdx.x * 128;
    int KK  = mode ? 512 : 256;

    const float* Ag = nullptr;   // mode 0 fixed A source
    const float* Ybase;
    int mbase;
    if (mode == 0) {
        if (m0 < 256) { Ag = d_M + (size_t)m0 * NC;         Ybase = d_g; mbase = m0; }
        else          { Ag = Wv  + (size_t)(m0 - 256) * NC; Ybase = d_v; mbase = m0 - 256; }
    } else {
        Ybase = out; mbase = m0;
    }

    float mn = 0.f, rs = 0.f;
    if (mode) { mn = d_mean[b]; rs = d_rstd[b]; }

    int lane = tid & 31, w = tid >> 5;
    int g = lane >> 2, tg = lane & 3;
    int wm = (w & 1) * 64, wn = (w >> 1) * 32;

    float acc[4][4][4];
#pragma unroll
    for (int mt = 0; mt < 4; mt++)
#pragma unroll
        for (int nt = 0; nt < 4; nt++)
#pragma unroll
            for (int i = 0; i < 4; i++) acc[mt][nt][i] = 0.f;

#pragma unroll 1
    for (int k0 = 0; k0 < KK; k0 += 32) {
        // ---- stage A chunk [128][32] (cvt to tf32) ----
        const float* Asrc;
        int kc;
        if (mode == 0) { Asrc = Ag; kc = k0; }
        else {
            Asrc = ((k0 < 256) ? Wout : d_W2) + (size_t)m0 * NC;
            kc = k0 & 255;
        }
#pragma unroll
        for (int j = 0; j < 4; j++) {
            int f = tid + 256 * j;
            int r = f >> 3, s = (f & 7) * 4;
            float4 a = *(const float4*)(Asrc + (size_t)r * NC + kc + s);
            uint4 t;
            t.x = f2tf(a.x); t.y = f2tf(a.y); t.z = f2tf(a.z); t.w = f2tf(a.w);
            *(uint4*)&As[r][s] = t;
        }
        // ---- stage B chunk [32][128] (cvt to tf32; mode1 k>=256: gn+relu) ----
#pragma unroll
        for (int j = 0; j < 4; j++) {
            int f = tid + 256 * j;
            int kr = f >> 5, cl = (f & 31) * 4;
            int kg = k0 + kr;
            float4 v;
            if (!mode || kg < 256) {
                v = *(const float4*)(x + ((size_t)b * NC + kg) * NL + l0 + cl);
            } else {
                int c = kg - 256;
                v = *(const float4*)(d_virt + ((size_t)b * NC + c) * NL + l0 + cl);
                float gsc = gamma[c] * rs;
                float bt  = beta[c] - mn * gsc;
                v.x = fmaxf(fmaf(v.x, gsc, bt), 0.f);
                v.y = fmaxf(fmaf(v.y, gsc, bt), 0.f);
                v.z = fmaxf(fmaf(v.z, gsc, bt), 0.f);
                v.w = fmaxf(fmaf(v.w, gsc, bt), 0.f);
            }
            uint4 t;
            t.x = f2tf(v.x); t.y = f2tf(v.y); t.z = f2tf(v.z); t.w = f2tf(v.w);
            *(uint4*)&Bs[kr][cl] = t;
        }
        __syncthreads();

        // ---- compute: 4 k8-steps x 16 mma ----
#pragma unroll
        for (int ks = 0; ks < 4; ks++) {
            int kb = ks * 8;
            uint32_t bf[4][2];
#pragma unroll
            for (int nt = 0; nt < 4; nt++) {
                bf[nt][0] = *(uint32_t*)&Bs[kb + tg][wn + nt * 8 + g];
                bf[nt][1] = *(uint32_t*)&Bs[kb + tg + 4][wn + nt * 8 + g];
            }
            uint32_t af[4][4];
#pragma unroll
            for (int mt = 0; mt < 4; mt++) {
                int rb = wm + mt * 16;
                af[mt][0] = *(uint32_t*)&As[rb + g][kb + tg];
                af[mt][1] = *(uint32_t*)&As[rb + g + 8][kb + tg];
                af[mt][2] = *(uint32_t*)&As[rb + g][kb + tg + 4];
                af[mt][3] = *(uint32_t*)&As[rb + g + 8][kb + tg + 4];
            }
#pragma unroll
            for (int mt = 0; mt < 4; mt++)
#pragma unroll
                for (int nt = 0; nt < 4; nt++)
                    mma_tf32(acc[mt][nt], af[mt], bf[nt]);
        }
        __syncthreads();
    }

    // ---- epilogue: fp32 stores ----
#pragma unroll
    for (int mt = 0; mt < 4; mt++) {
        int m = mbase + wm + mt * 16 + g;
        float* y0 = (float*)Ybase + ((size_t)b * NC + m) * NL + l0;
        float* y1 = (float*)Ybase + ((size_t)b * NC + m + 8) * NL + l0;
#pragma unroll
        for (int nt = 0; nt < 4; nt++) {
            int l = wn + nt * 8 + 2 * tg;
            y0[l]     = acc[mt][nt][0];
            y0[l + 1] = acc[mt][nt][1];
            y1[l]     = acc[mt][nt][2];
            y1[l + 1] = acc[mt][nt][3];
        }
    }
}

// ---------------- K2: attention per l-tile (LT=4) --------------------------
#define SP_STR 260
#define SX_STR 36
#define SV_STR 132
#define K2_SMEM ((64 * SP_STR + 64 * SV_STR) * 4)

__global__ __launch_bounds__(256, 2) void k2_attn(const float* __restrict__ x) {
    extern __shared__ float smemf[];
    float* sP = smemf;
    float* sX = smemf + 64 * SP_STR;
    float* sG = sX + 64 * SX_STR;
    float* sV = smemf + 64 * SP_STR;

    int tid = threadIdx.x;
    int lt  = blockIdx.x * LT;
    int tb  = tid & 15;
    int td  = tid >> 4;

    float acc[4][4][4];
#pragma unroll
    for (int i = 0; i < 4; i++)
#pragma unroll
        for (int j = 0; j < 4; j++)
#pragma unroll
            for (int l = 0; l < 4; l++) acc[i][j][l] = 0.f;

    for (int c0 = 0; c0 < NC; c0 += 8) {
#pragma unroll
        for (int j = 0; j < 2; j++) {
            int t  = tid + j * 256;
            int bb = t >> 3, cc = t & 7;
            *(float4*)&sX[bb * SX_STR + cc * 4] =
                *(const float4*)(x   + ((size_t)bb * NC + c0 + cc) * NL + lt);
            *(float4*)&sG[bb * SX_STR + cc * 4] =
                *(const float4*)(d_g + ((size_t)bb * NC + c0 + cc) * NL + lt);
        }
        __syncthreads();
#pragma unroll
        for (int cc = 0; cc < 8; cc++) {
            float4 xv[4], gv[4];
#pragma unroll
            for (int i = 0; i < 4; i++)
                xv[i] = *(float4*)&sX[(tb + 16 * i) * SX_STR + cc * 4];
#pragma unroll
            for (int i = 0; i < 4; i++)
                gv[i] = *(float4*)&sG[(td + 16 * i) * SX_STR + cc * 4];
#pragma unroll
            for (int bi = 0; bi < 4; bi++)
#pragma unroll
                for (int di = 0; di < 4; di++) {
                    acc[bi][di][0] += xv[bi].x * gv[di].x;
                    acc[bi][di][1] += xv[bi].y * gv[di].y;
                    acc[bi][di][2] += xv[bi].z * gv[di].z;
                    acc[bi][di][3] += xv[bi].w * gv[di].w;
                }
        }
        __syncthreads();
    }
#pragma unroll
    for (int bi = 0; bi < 4; bi++)
#pragma unroll
        for (int di = 0; di < 4; di++)
#pragma unroll
            for (int l = 0; l < 4; l++)
                sP[(tb + 16 * bi) * SP_STR + (td + 16 * di) * 4 + l] = acc[bi][di][l];
    __syncthreads();

    {
        int b = tid >> 2, l = tid & 3;
        float* row = sP + b * SP_STR + l;
        float mx = -1e30f;
#pragma unroll 8
        for (int d = 0; d < 64; d++) mx = fmaxf(mx, row[d * 4]);
        float s = 0.f;
#pragma unroll 8
        for (int d = 0; d < 64; d++) {
            float e = __expf(row[d * 4] - mx);
            row[d * 4] = e;
            s += e;
        }
        float inv = 1.f / s;
#pragma unroll 8
        for (int d = 0; d < 64; d++) row[d * 4] *= inv;
    }
    __syncthreads();

    int tc = tid >> 4;
    for (int c0 = 0; c0 < NC; c0 += 32) {
#pragma unroll
        for (int j = 0; j < 8; j++) {
            int t  = tid + j * 256;
            int dd = t >> 5, ci = t & 31;
            *(float4*)&sV[dd * SV_STR + ci * 4] =
                *(const float4*)(d_v + ((size_t)dd * NC + c0 + ci) * NL + lt);
        }
        __syncthreads();
        float a3[4][2][4];
#pragma unroll
        for (int i = 0; i < 4; i++)
#pragma unroll
            for (int j = 0; j < 2; j++)
#pragma unroll
                for (int l = 0; l < 4; l++) a3[i][j][l] = 0.f;
#pragma unroll 4
        for (int d = 0; d < 64; d++) {
            float4 p[4];
#pragma unroll
            for (int i = 0; i < 4; i++)
                p[i] = *(float4*)&sP[(tb + 16 * i) * SP_STR + d * 4];
            float4 vv[2];
#pragma unroll
            for (int i = 0; i < 2; i++)
                vv[i] = *(float4*)&sV[d * SV_STR + (tc + 16 * i) * 4];
#pragma unroll
            for (int bi = 0; bi < 4; bi++)
#pragma unroll
                for (int ci = 0; ci < 2; ci++) {
                    a3[bi][ci][0] += p[bi].x * vv[ci].x;
                    a3[bi][ci][1] += p[bi].y * vv[ci].y;
                    a3[bi][ci][2] += p[bi].z * vv[ci].z;
                    a3[bi][ci][3] += p[bi].w * vv[ci].w;
                }
        }
#pragma unroll
        for (int bi = 0; bi < 4; bi++)
#pragma unroll
            for (int ci = 0; ci < 2; ci++) {
                float4 o4 = make_float4(a3[bi][ci][0], a3[bi][ci][1],
                                        a3[bi][ci][2], a3[bi][ci][3]);
                *(float4*)(d_virt + ((size_t)(tb + 16 * bi) * NC + c0 + tc + 16 * ci) * NL + lt) = o4;
            }
        __syncthreads();
    }
}

// ---------------- K3: per-batch GroupNorm stats (deterministic) ------------
__global__ void k3_stats() {
    int b   = blockIdx.x;
    int tid = threadIdx.x;
    const float4* p = (const float4*)(d_virt + (size_t)b * NC * NL);
    float s = 0.f, q = 0.f;
    for (int j = 0; j < 1024; j++) {
        float4 v = p[tid + j * 256];
        s += v.x + v.y + v.z + v.w;
        q += v.x * v.x + v.y * v.y + v.z * v.z + v.w * v.w;
    }
    __shared__ float ss[256], sq[256];
    ss[tid] = s; sq[tid] = q;
    __syncthreads();
    for (int st = 128; st > 0; st >>= 1) {
        if (tid < st) { ss[tid] += ss[tid + st]; sq[tid] += sq[tid + st]; }
        __syncthreads();
    }
    if (tid == 0) {
        float N    = (float)(NC * NL);
        float mean = ss[0] / N;
        float var  = sq[0] / N - mean * mean;
        d_mean[b] = mean;
        d_rstd[b] = rsqrtf(var + 1e-5f);
    }
}

// ---------------- launch ----------------------------------------------------
extern "C" void kernel_launch(void* const* d_in, const int* in_sizes, int n_in,
                              void* d_out, int out_size) {
    const float* x     = (const float*)d_in[0];
    const float* Wq    = (const float*)d_in[1];
    const float* Wk    = (const float*)d_in[2];
    const float* Wv    = (const float*)d_in[3];
    const float* Wc    = (const float*)d_in[4];
    const float* Wout  = (const float*)d_in[5];
    const float* gamma = (const float*)d_in[6];
    const float* beta  = (const float*)d_in[7];
    float* out = (float*)d_out;

    cudaFuncSetAttribute(k2_attn, cudaFuncAttributeMaxDynamicSharedMemorySize, K2_SMEM);

    dim3 b16(16, 16);
    k0_M <<<dim3(16, 16), b16>>>(Wq, Wk);
    k0_W2<<<dim3(16, 16), b16>>>(Wout, Wc);

    k_gemm<<<dim3(4, NL / 128, NB), 256>>>(0, nullptr, Wv, x, Wout, gamma, beta);

    k2_attn<<<NL / LT, 256, K2_SMEM>>>(x);
    k3_stats<<<NB, 256>>>();

    k_gemm<<<dim3(2, NL / 128, NB), 256>>>(1, out, Wv, x, Wout, gamma, beta);
}